// round 13
// baseline (speedup 1.0000x reference)
#include <cuda_runtime.h>
#include <cstdint>
#include <math.h>

#define N_NODES 200000
#define D_FEAT  256
#define P_PROMPT 10
#define E_ORIG  3200000
#define T_SENT  (N_NODES + P_PROMPT)                               // 200010
#define M_MAX   (E_ORIG + P_PROMPT*P_PROMPT + 2*P_PROMPT*N_NODES)  // 7200100

#define NB_MOM  1000
#define ROWS_PER_MOM (N_NODES / NB_MOM)   // 200
#define NPART (NB_MOM * 4)                // 4000 partial rows

#define CHUNK 256
#define NCHUNK ((N_NODES + CHUNK - 1) / CHUNK)  // 782

#define BUCKET_CAP 64
#define NB_SCAN 196   // ceil(200010/1024)

// thresholds: exact-logit equivalents of sigmoid(d) > (float)0.4 / (float)0.2
#define THR_CROSS (-0.4054650832728957)
#define THR_INNER (-1.3862943424934391)
#define THR_CROSS_F (-0.40546508f)
#define REFINE_WIN 3e-3f
#define REFINE_CAP 16384

// k_cross tiling: 256 threads, 1 row/thread, CROWS == CHUNK == 256
// single-buffered 16-col chunks (4 float4), stride 5 f4 (conflict-free)
#define CTHREADS 256
#define CROWS 256
#define NCH   16
#define F4C   4
#define F4PR  5
#define TILE_F4 (CROWS * F4PR)                       // 1280 f4 = 20 KB
#define NBLK_CROSS ((N_NODES + CROWS - 1) / CROWS)   // 782 == NCHUNK
#define CROSS_SMEM_FLOATS (TILE_F4 * 4 + P_PROMPT * D_FEAT)
#define CROSS_SMEM_BYTES  (CROSS_SMEM_FLOATS * 4)    // 30720 B

// ---------------- static device scratch (no allocations allowed) ----------------
__device__ float4   g_mompart[NPART][D_FEAT];    // (sum, sum_err, sumsq, sumsq_err)
__device__ float2   g_stats[D_FEAT];             // (mu_of, sig_of)
__device__ float    g_pprime[P_PROMPT * D_FEAT];
__device__ unsigned g_crossmask[N_NODES];
__device__ unsigned g_innerbits[P_PROMPT];
__device__ int      g_cnt[N_NODES];              // zero-init; re-zeroed in fused scan(0)
__device__ int      g_boff[N_NODES + 1];
__device__ int      g_cursor[N_NODES];
__device__ int      g_bucket[E_ORIG];
__device__ int      g_fcnt[T_SENT];
__device__ int      g_outoff[T_SENT + 1];
__device__ int      g_cpart[NCHUNK * P_PROMPT];
__device__ int      g_choff[NCHUNK * P_PROMPT];
__device__ int      g_ccnt[P_PROMPT];
__device__ int2     g_refine[REFINE_CAP];
__device__ int      g_nrefine;
__device__ unsigned long long g_sstat[2][NB_SCAN];   // decoupled-lookback status

// ---------------- kernels ----------------

// 2Sum accumulate v into (s, e): exact error tracking in f32
__device__ __forceinline__ void acc2(float &s, float &e, float v) {
    float t = s + v;
    float z = t - s;
    e += (s - (t - z)) + (v - z);
    s = t;
}

// Pass 1: read-only per-column partial moments (copy runs later, overlapped).
__global__ void k_moments(const float* __restrict__ x) {
    int blk = blockIdx.x;              // NB_MOM
    int cg   = threadIdx.x & 63;       // column group of 4
    int rsub = threadIdx.x >> 6;       // 0..3
    float s[4]  = {0.f, 0.f, 0.f, 0.f};
    float se[4] = {0.f, 0.f, 0.f, 0.f};
    float q[4]  = {0.f, 0.f, 0.f, 0.f};
    float qe[4] = {0.f, 0.f, 0.f, 0.f};
    int base_r = blk * ROWS_PER_MOM + rsub;
    #pragma unroll 4
    for (int it = 0; it < ROWS_PER_MOM / 4; it++) {
        int r = base_r + it * 4;
        float4 v = reinterpret_cast<const float4*>(x + (size_t)r * D_FEAT)[cg];
        float vv[4] = {v.x, v.y, v.z, v.w};
        #pragma unroll
        for (int k = 0; k < 4; k++) {
            acc2(s[k], se[k], vv[k]);
            float p = vv[k] * vv[k];
            float perr = fmaf(vv[k], vv[k], -p);
            acc2(q[k], qe[k], p);
            qe[k] += perr;
        }
    }
    int prow = blk * 4 + rsub;
    #pragma unroll
    for (int k = 0; k < 4; k++)
        g_mompart[prow][cg * 4 + k] = make_float4(s[k], se[k], q[k], qe[k]);
}

// Parallel per-column moment reduction: one block per column, f64 tree.
__global__ void k_colstats() {
    __shared__ double shs[128], shq[128];
    int col = blockIdx.x;        // 256 blocks
    int t = threadIdx.x;         // 128 threads
    if (col == 0 && t == 0) g_nrefine = 0;
    double ds = 0.0, dq = 0.0;
    for (int b = t; b < NPART; b += 128) {
        float4 m = g_mompart[b][col];
        ds += (double)m.x + (double)m.y;
        dq += (double)m.z + (double)m.w;
    }
    shs[t] = ds; shq[t] = dq;
    __syncthreads();
    for (int off = 64; off; off >>= 1) {
        if (t < off) { shs[t] += shs[t + off]; shq[t] += shq[t + off]; }
        __syncthreads();
    }
    if (t == 0) {
        double S = shs[0], Q = shq[0];
        double mu_o  = S / (double)N_NODES;
        double var_o = (Q - S * S / (double)N_NODES) / (double)(N_NODES - 1);
        g_stats[col] = make_float2((float)mu_o, __fadd_rn((float)sqrt(var_o), 1e-8f));
    }
}

// Prompt stats + p_prime (f32 per-op match), write prompt rows, inner bits
// (f64, 8-way split per dot + shuffle reduce).
__global__ void k_finalize(const float* __restrict__ prompt, float* __restrict__ outx) {
    __shared__ float sh_pp[P_PROMPT][D_FEAT];   // 10 KB
    int tid = threadIdx.x;                       // 1024 threads

    if (tid < P_PROMPT) g_innerbits[tid] = 0;

    if (tid < D_FEAT) {
        int col = tid;
        float2 st = g_stats[col];
        float mu_of = st.x, sig_of = st.y;

        float pv[P_PROMPT];
        double ps = 0.0;
        for (int i = 0; i < P_PROMPT; i++) { pv[i] = prompt[i * D_FEAT + col]; ps += (double)pv[i]; }
        double mu_p = ps / (double)P_PROMPT;
        double pq = 0.0;
        for (int i = 0; i < P_PROMPT; i++) { double d = (double)pv[i] - mu_p; pq += d * d; }
        float mu_pf  = (float)mu_p;
        float sig_pf = __fadd_rn((float)sqrt(pq / (double)(P_PROMPT - 1)), 1e-8f);

        for (int i = 0; i < P_PROMPT; i++) {
            float pp = __fadd_rn(__fmul_rn(__fdiv_rn(__fsub_rn(pv[i], mu_pf), sig_pf), sig_of), mu_of);
            g_pprime[i * D_FEAT + col] = pp;
            sh_pp[i][col] = pp;
            outx[(size_t)(N_NODES + i) * D_FEAT + col] = pp;
        }
    }
    __syncthreads();

    if (tid < P_PROMPT * P_PROMPT * 8) {         // warps 0..24 fully active
        int pair = tid >> 3, l8 = tid & 7;
        int i = pair / P_PROMPT, j = pair % P_PROMPT;
        const float* a = sh_pp[i];
        const float* b = sh_pp[j];
        double s = 0.0;
        int c0 = l8 * 32;
        #pragma unroll 1
        for (int c = c0; c < c0 + 32; c++)
            s = fma((double)a[c], (double)b[c], s);
        #pragma unroll
        for (int off = 4; off; off >>= 1)
            s += __shfl_down_sync(0xffffffffu, s, off, 8);
        if (l8 == 0 && s > THR_INNER) atomicOr(&g_innerbits[i], 1u << j);
    }
}

// Cross similarities + fused per-chunk counts. 1 row/thread, single-buffered
// 16-col chunks; natural register allocation (~64 regs, 4 blocks/SM). R9 form.
__global__ void k_cross(const float* __restrict__ x) {
    extern __shared__ float dyn[];
    float4* sh_x  = reinterpret_cast<float4*>(dyn);       // [CROWS][F4PR]
    float*  sh_pp = dyn + TILE_F4 * 4;                    // [P_PROMPT][D_FEAT]
    __shared__ int wcnt[CTHREADS / 32][P_PROMPT];
    int tid = threadIdx.x;
    for (int t = tid; t < P_PROMPT * D_FEAT; t += CTHREADS) sh_pp[t] = g_pprime[t];
    int row0 = blockIdx.x * CROWS;

    float acc[P_PROMPT];
    #pragma unroll
    for (int i = 0; i < P_PROMPT; i++) acc[i] = 0.f;

    const float4* pp4 = reinterpret_cast<const float4*>(sh_pp);
    #pragma unroll 1
    for (int ch = 0; ch < NCH; ch++) {
        __syncthreads();
        #pragma unroll
        for (int l = 0; l < 4; l++) {
            int idx = l * CTHREADS + tid;
            int r = idx >> 2, f = idx & 3;
            int gr = row0 + r;
            float4 v = (gr < N_NODES)
                ? reinterpret_cast<const float4*>(x + (size_t)gr * D_FEAT)[ch * F4C + f]
                : make_float4(0.f, 0.f, 0.f, 0.f);
            sh_x[r * F4PR + f] = v;
        }
        __syncthreads();
        #pragma unroll
        for (int f = 0; f < F4C; f++) {
            float4 pv4[P_PROMPT];
            #pragma unroll
            for (int i = 0; i < P_PROMPT; i++)
                pv4[i] = pp4[i * (D_FEAT / 4) + ch * F4C + f];   // warp-broadcast LDS
            float4 xv = sh_x[tid * F4PR + f];
            #pragma unroll
            for (int i = 0; i < P_PROMPT; i++) {
                acc[i] = fmaf(xv.x, pv4[i].x, acc[i]);
                acc[i] = fmaf(xv.y, pv4[i].y, acc[i]);
                acc[i] = fmaf(xv.z, pv4[i].z, acc[i]);
                acc[i] = fmaf(xv.w, pv4[i].w, acc[i]);
            }
        }
    }

    int gr = row0 + tid;
    unsigned m = 0;
    if (gr < N_NODES) {
        #pragma unroll
        for (int i = 0; i < P_PROMPT; i++) {
            float a = acc[i];
            if (fabsf(a - THR_CROSS_F) < REFINE_WIN) {
                int pos = atomicAdd(&g_nrefine, 1);
                if (pos < REFINE_CAP) g_refine[pos] = make_int2(gr, i);
            }
            if ((double)a > THR_CROSS) m |= (1u << i);
        }
        g_crossmask[gr] = m;
    }

    // fused per-chunk per-i counts (chunk == blockIdx.x)
    int w = tid >> 5, lane = tid & 31;
    #pragma unroll
    for (int i = 0; i < P_PROMPT; i++) {
        unsigned bal = __ballot_sync(0xffffffffu, (m >> i) & 1u);
        if (lane == 0) wcnt[w][i] = __popc(bal);
    }
    __syncthreads();
    if (tid < P_PROMPT) {
        int t = 0;
        #pragma unroll
        for (int w2 = 0; w2 < CTHREADS / 32; w2++) t += wcnt[w2][tid];
        g_cpart[blockIdx.x * P_PROMPT + tid] = t;
    }
}

// Exact f64 recompute of near-threshold dots; fix mask bits AND chunk counts.
__global__ void k_refine(const float* __restrict__ x) {
    int t = blockIdx.x * blockDim.x + threadIdx.x;
    int n = g_nrefine;
    if (n > REFINE_CAP) n = REFINE_CAP;
    if (t >= n) return;
    int2 it = g_refine[t];
    const float* xr = x + (size_t)it.x * D_FEAT;
    const float* pp = g_pprime + it.y * D_FEAT;
    double s = 0.0;
    #pragma unroll 1
    for (int c = 0; c < D_FEAT; c++)
        s = fma((double)xr[c], (double)pp[c], s);
    unsigned bit = 1u << it.y;
    bool dec = (s > THR_CROSS);
    bool oldbit = (g_crossmask[it.x] >> it.y) & 1u;
    if (dec != oldbit) {
        if (dec) atomicOr(&g_crossmask[it.x], bit);
        else     atomicAnd(&g_crossmask[it.x], ~bit);
        atomicAdd(&g_cpart[(it.x / CHUNK) * P_PROMPT + it.y], dec ? 1 : -1);
    }
}

// Exclusive scan of chunk counts per i; totals -> g_ccnt.
__global__ void k_cross_spine() {
    __shared__ int sh[NCHUNK * P_PROMPT];   // ~31 KB
    for (int t = threadIdx.x; t < NCHUNK * P_PROMPT; t += blockDim.x) sh[t] = g_cpart[t];
    __syncthreads();
    if (threadIdx.x < P_PROMPT) {
        int i = threadIdx.x, run = 0;
        for (int c = 0; c < NCHUNK; c++) {
            int v = sh[c * P_PROMPT + i];
            g_choff[c * P_PROMPT + i] = run;
            run += v;
        }
        g_ccnt[i] = run;
    }
}

// hist also zeroes scan-0 lookback status (runs before fused scan 0 in-stream)
__global__ void k_hist(const int* __restrict__ src) {
    int g = blockIdx.x * blockDim.x + threadIdx.x;
    if (g < NB_SCAN) g_sstat[0][g] = 0ULL;
    if (g < E_ORIG) atomicAdd(&g_cnt[src[g]], 1);
}

// generic params, selected by mode (0: cnt->boff, 1: fcnt->outoff)
__device__ __forceinline__ void scan_params(int mode, const int*& in, int*& out, int& n) {
    if (mode == 0) { in = g_cnt;  out = g_boff;   n = N_NODES; }
    else           { in = g_fcnt; out = g_outoff; n = T_SENT;  }
}

// Single-pass decoupled-lookback exclusive scan. Status word packs
// (value << 2) | flag; flag: 0=empty, 1=aggregate, 2=inclusive-prefix.
__global__ void k_scan_fused(int mode) {
    const int* in; int* out; int n;
    scan_params(mode, in, out, n);
    __shared__ int sh[1024];
    __shared__ int sh_off;
    int tid = threadIdx.x;
    int bid = blockIdx.x;
    int g = bid * 1024 + tid;
    int v = (g < n) ? in[g] : 0;
    sh[tid] = v;
    __syncthreads();
    for (int off = 1; off < 1024; off <<= 1) {
        int t = (tid >= off) ? sh[tid - off] : 0;
        __syncthreads();
        sh[tid] += t;
        __syncthreads();
    }
    if (tid == 0) {
        int agg = sh[1023];
        if (bid == 0) {
            atomicExch(&g_sstat[mode][0], ((unsigned long long)(unsigned)agg << 2) | 2ULL);
            sh_off = 0;
        } else {
            atomicExch(&g_sstat[mode][bid], ((unsigned long long)(unsigned)agg << 2) | 1ULL);
            int excl = 0;
            int j = bid - 1;
            while (j >= 0) {
                unsigned long long s = *(volatile unsigned long long*)&g_sstat[mode][j];
                unsigned fl = (unsigned)(s & 3ULL);
                if (fl == 2u) { excl += (int)(s >> 2); break; }
                if (fl == 1u) { excl += (int)(s >> 2); j--; }
            }
            atomicExch(&g_sstat[mode][bid],
                       ((unsigned long long)(unsigned)(excl + agg) << 2) | 2ULL);
            sh_off = excl;
        }
    }
    __syncthreads();
    if (g < n) {
        int incl = sh[tid] + sh_off;
        int excl = incl - v;
        out[g] = excl;
        if (mode == 0) {
            g_cursor[g] = excl;
            g_cnt[g] = 0;             // re-zero for next graph replay (after last read)
        }
        if (g == n - 1) out[n] = incl;
    }
}

__global__ void k_scatter(const int* __restrict__ src, const int* __restrict__ dst) {
    int g = blockIdx.x * blockDim.x + threadIdx.x;
    if (g < E_ORIG) {
        int s = src[g];
        int pos = atomicAdd(&g_cursor[s], 1);
        g_bucket[pos] = dst[g];
    }
}

// Per-src insertion sort + dedup; working array in bank-conflict-free smem.
// Also zeroes scan-1 lookback status (runs before fused scan 1 in-stream).
__global__ void k_sortbuckets() {
    __shared__ int loc[BUCKET_CAP * 128];      // 32 KB; loc[k][tid] layout
    int tid = threadIdx.x;                     // 128 threads
    int j = blockIdx.x * 128 + tid;
    if (j < NB_SCAN) g_sstat[1][j] = 0ULL;
    #define LOC(k) loc[(k) * 128 + tid]
    if (j < N_NODES) {
        int base = g_boff[j];
        int len = g_boff[j + 1] - base;
        int L = 0;
        for (int k = 0; k < len; k++) {
            int v = g_bucket[base + k];
            int p = L;
            while (p > 0 && LOC(p - 1) > v) p--;
            if (p > 0 && LOC(p - 1) == v) continue;     // duplicate
            if (L < BUCKET_CAP) {
                for (int q = L; q > p; q--) LOC(q) = LOC(q - 1);
                LOC(p) = v;
                L++;
            }
        }
        for (int k = 0; k < L; k++) g_bucket[base + k] = LOC(k);
        g_fcnt[j] = L + __popc(g_crossmask[j]);
    } else if (j < T_SENT) {
        int i = j - N_NODES;
        g_fcnt[j] = g_ccnt[i] + __popc(g_innerbits[i]);
    }
    #undef LOC
}

// Emit edges with src < N: warp-per-node, lane-parallel coalesced stores.
__global__ void k_emit_orig(float* __restrict__ out_src, float* __restrict__ out_dst) {
    int wid = threadIdx.x >> 5;
    int lane = threadIdx.x & 31;
    int j = blockIdx.x * 8 + wid;
    if (j >= N_NODES) return;
    unsigned m = g_crossmask[j];
    int base = g_outoff[j];
    int bb = g_boff[j];
    int U = g_fcnt[j] - __popc(m);
    float fj = (float)j;
    for (int k = lane; k < U; k += 32) {
        out_src[base + k] = fj;
        out_dst[base + k] = (float)g_bucket[bb + k];
    }
    int nb = __popc(m);
    if (lane < nb) {
        unsigned mm = m;
        for (int t = 0; t < lane; t++) mm &= mm - 1;
        int b = __ffs(mm) - 1;
        out_src[base + U + lane] = fj;
        out_dst[base + U + lane] = (float)(N_NODES + b);
    }
}

// Emit cross edges (N+i, j) + inner prompt-prompt edges (block 0 tail).
__global__ void k_emit_cross(float* __restrict__ out_src, float* __restrict__ out_dst) {
    int chunk = blockIdx.x;
    int j = chunk * CHUNK + threadIdx.x;
    unsigned m = (j < N_NODES) ? g_crossmask[j] : 0u;
    __shared__ int wcnt[8][P_PROMPT];
    __shared__ int woff[8][P_PROMPT];
    int w = threadIdx.x >> 5, lane = threadIdx.x & 31;
    unsigned bal[P_PROMPT];
    #pragma unroll
    for (int i = 0; i < P_PROMPT; i++) {
        bal[i] = __ballot_sync(0xffffffffu, (m >> i) & 1u);
        if (lane == 0) wcnt[w][i] = __popc(bal[i]);
    }
    __syncthreads();
    if (threadIdx.x < P_PROMPT) {
        int run = 0;
        for (int w2 = 0; w2 < 8; w2++) { woff[w2][threadIdx.x] = run; run += wcnt[w2][threadIdx.x]; }
    }
    __syncthreads();
    unsigned ltmask = (1u << lane) - 1u;
    #pragma unroll
    for (int i = 0; i < P_PROMPT; i++) {
        if ((m >> i) & 1u) {
            int pos = g_outoff[N_NODES + i] + g_choff[chunk * P_PROMPT + i]
                      + woff[w][i] + __popc(bal[i] & ltmask);
            out_src[pos] = (float)(N_NODES + i);
            out_dst[pos] = (float)j;
        }
    }
    // inner prompt-prompt edges, emitted once by block 0
    if (chunk == 0 && threadIdx.x < P_PROMPT) {
        int i = threadIdx.x;
        int pos = g_outoff[N_NODES + i] + g_ccnt[i];
        unsigned b = g_innerbits[i];
        for (int jj = 0; jj < P_PROMPT; jj++) {
            if ((b >> jj) & 1u) {
                out_src[pos] = (float)(N_NODES + i);
                out_dst[pos] = (float)(N_NODES + jj);
                pos++;
            }
        }
    }
}

// Padding fill, float4-vectorized (tail handled scalar).
__global__ void k_fill(float* __restrict__ out_src, float* __restrict__ out_dst,
                       float* __restrict__ out_w) {
    int g4 = blockIdx.x * blockDim.x + threadIdx.x;   // float4 index
    int g = g4 * 4;
    if (g >= M_MAX) return;
    int M = __ldg(&g_outoff[T_SENT]);
    float4 sent = make_float4((float)T_SENT, (float)T_SENT, (float)T_SENT, (float)T_SENT);
    if (g + 4 <= M_MAX) {
        if (g >= M) {
            reinterpret_cast<float4*>(out_src)[g4] = sent;
            reinterpret_cast<float4*>(out_dst)[g4] = sent;
            reinterpret_cast<float4*>(out_w)[g4] = make_float4(0.f, 0.f, 0.f, 0.f);
        } else if (g + 4 > M) {
            for (int k = 0; k < 4; k++) {
                int idx = g + k;
                if (idx >= M) {
                    out_src[idx] = (float)T_SENT;
                    out_dst[idx] = (float)T_SENT;
                }
                out_w[idx] = (idx < M) ? 1.0f : 0.0f;
            }
        } else {
            reinterpret_cast<float4*>(out_w)[g4] = make_float4(1.f, 1.f, 1.f, 1.f);
        }
    } else {
        for (int idx = g; idx < M_MAX; idx++) {
            if (idx >= M) {
                out_src[idx] = (float)T_SENT;
                out_dst[idx] = (float)T_SENT;
            }
            out_w[idx] = (idx < M) ? 1.0f : 0.0f;
        }
    }
}

// ---------------- launch ----------------
extern "C" void kernel_launch(void* const* d_in, const int* in_sizes, int n_in,
                              void* d_out, int out_size) {
    (void)n_in; (void)out_size;
    const float* x  = (const float*)d_in[0];
    const int*   ei = (const int*)d_in[1];       // [2, E]: src then dst
    const float* pf = (const float*)d_in[2];
    const int* src = ei;
    const int* dst = ei + E_ORIG;
    (void)in_sizes;

    float* out     = (float*)d_out;
    float* out_x   = out;
    float* out_src = out + (size_t)T_SENT * D_FEAT;
    float* out_dst = out_src + M_MAX;
    float* out_w   = out_dst + M_MAX;

    cudaFuncSetAttribute(k_cross, cudaFuncAttributeMaxDynamicSharedMemorySize,
                         CROSS_SMEM_BYTES);

    cudaStream_t s1;
    cudaStreamCreateWithFlags(&s1, cudaStreamNonBlocking);
    cudaEvent_t evRoot, evE, evM, evF;
    cudaEventCreateWithFlags(&evRoot, cudaEventDisableTiming);
    cudaEventCreateWithFlags(&evE,   cudaEventDisableTiming);
    cudaEventCreateWithFlags(&evM,   cudaEventDisableTiming);
    cudaEventCreateWithFlags(&evF,   cudaEventDisableTiming);

    // fork side stream
    cudaEventRecord(evRoot, 0);
    cudaStreamWaitEvent(s1, evRoot, 0);

    // --- side stream s1: edge path first (concurrent with x-path compute) ---
    k_hist<<<(E_ORIG + 255) / 256, 256, 0, s1>>>(src);
    k_scan_fused<<<NB_SCAN, 1024, 0, s1>>>(0);
    k_scatter<<<(E_ORIG + 255) / 256, 256, 0, s1>>>(src, dst);
    cudaEventRecord(evE, s1);
    // x -> out_x copy: no deps; scheduled here so it overlaps the
    // bandwidth-idle sortbuckets/scan1/emit phase on stream 0, NOT the
    // x-streaming phase (R12 lesson: copy-vs-moments contention).
    cudaMemcpyAsync(out_x, x, (size_t)N_NODES * D_FEAT * sizeof(float),
                    cudaMemcpyDeviceToDevice, s1);

    // --- x path (stream 0) ---
    k_moments<<<NB_MOM, 256>>>(x);
    k_colstats<<<D_FEAT, 128>>>();
    k_finalize<<<1, 1024>>>(pf, out_x);
    k_cross<<<NBLK_CROSS, CTHREADS, CROSS_SMEM_BYTES>>>(x);
    k_refine<<<REFINE_CAP / 256, 256>>>(x);
    k_cross_spine<<<1, 1024>>>();

    // join: sortbuckets needs both paths
    cudaStreamWaitEvent(0, evE, 0);

    k_sortbuckets<<<(T_SENT + 127) / 128, 128>>>();
    k_scan_fused<<<NB_SCAN, 1024>>>(1);

    // fork fill (padding region, disjoint from emit writes) onto s1
    cudaEventRecord(evM, 0);
    cudaStreamWaitEvent(s1, evM, 0);
    k_fill<<<(M_MAX / 4 + 255) / 256, 256, 0, s1>>>(out_src, out_dst, out_w);

    k_emit_orig<<<(N_NODES + 7) / 8, 256>>>(out_src, out_dst);
    k_emit_cross<<<NCHUNK, 256>>>(out_src, out_dst);

    // join fill + copy back
    cudaEventRecord(evF, s1);
    cudaStreamWaitEvent(0, evF, 0);

    cudaEventDestroy(evRoot);
    cudaEventDestroy(evE);
    cudaEventDestroy(evM);
    cudaEventDestroy(evF);
    cudaStreamDestroy(s1);
}

// round 14
// speedup vs baseline: 1.2343x; 1.2343x over previous
#include <cuda_runtime.h>
#include <cstdint>
#include <math.h>

#define N_NODES 200000
#define D_FEAT  256
#define P_PROMPT 10
#define E_ORIG  3200000
#define T_SENT  (N_NODES + P_PROMPT)                               // 200010
#define M_MAX   (E_ORIG + P_PROMPT*P_PROMPT + 2*P_PROMPT*N_NODES)  // 7200100

#define NB_MOM  1000
#define ROWS_PER_MOM (N_NODES / NB_MOM)   // 200
#define NPART (NB_MOM * 4)                // 4000 partial rows

#define CHUNK 256
#define NCHUNK ((N_NODES + CHUNK - 1) / CHUNK)  // 782

#define BUCKET_CAP 64
#define NB_SCAN 196   // ceil(200010/1024)

// thresholds: exact-logit equivalents of sigmoid(d) > (float)0.4 / (float)0.2
#define THR_CROSS (-0.4054650832728957)
#define THR_INNER (-1.3862943424934391)
#define THR_CROSS_F (-0.40546508f)
#define REFINE_WIN 3e-3f
#define REFINE_CAP 16384

// k_cross tiling: 256 threads, 1 row/thread, CROWS == CHUNK == 256
// single-buffered 16-col chunks (4 float4), stride 5 f4 (conflict-free)
#define CTHREADS 256
#define CROWS 256
#define NCH   16
#define F4C   4
#define F4PR  5
#define TILE_F4 (CROWS * F4PR)                       // 1280 f4 = 20 KB
#define NBLK_CROSS ((N_NODES + CROWS - 1) / CROWS)   // 782 == NCHUNK
#define CROSS_SMEM_FLOATS (TILE_F4 * 4 + P_PROMPT * D_FEAT)
#define CROSS_SMEM_BYTES  (CROSS_SMEM_FLOATS * 4)    // 30720 B

// ---------------- static device scratch (no allocations allowed) ----------------
__device__ float4   g_mompart[NPART][D_FEAT];    // (sum, sum_err, sumsq, sumsq_err)
__device__ float2   g_stats[D_FEAT];             // (mu_of, sig_of)
__device__ float    g_pprime[P_PROMPT * D_FEAT];
__device__ unsigned g_crossmask[N_NODES];
__device__ unsigned g_innerbits[P_PROMPT];
__device__ int      g_cnt[N_NODES];              // zero-init; re-zeroed in fused scan(0)
__device__ int      g_boff[N_NODES + 1];
__device__ int      g_cursor[N_NODES];
__device__ int      g_bucket[E_ORIG];
__device__ int      g_fcnt[T_SENT];
__device__ int      g_outoff[T_SENT + 1];
__device__ int      g_cpart[NCHUNK * P_PROMPT];
__device__ int      g_choff[NCHUNK * P_PROMPT];
__device__ int      g_ccnt[P_PROMPT];
__device__ int2     g_refine[REFINE_CAP];
__device__ int      g_nrefine;
__device__ unsigned long long g_sstat[2][NB_SCAN];   // decoupled-lookback status

// ---------------- kernels ----------------

// 2Sum accumulate v into (s, e): exact error tracking in f32
__device__ __forceinline__ void acc2(float &s, float &e, float v) {
    float t = s + v;
    float z = t - s;
    e += (s - (t - z)) + (v - z);
    s = t;
}

// Pass 1: copy x -> out (x_combined head, float4) + per-column partial moments.
// R9-champion form: fused copy streams writes behind reads; cheapest placement.
__global__ void k_moments_copy(const float* __restrict__ x, float* __restrict__ outx) {
    int blk = blockIdx.x;              // NB_MOM
    int cg   = threadIdx.x & 63;       // column group of 4
    int rsub = threadIdx.x >> 6;       // 0..3
    float s[4]  = {0.f, 0.f, 0.f, 0.f};
    float se[4] = {0.f, 0.f, 0.f, 0.f};
    float q[4]  = {0.f, 0.f, 0.f, 0.f};
    float qe[4] = {0.f, 0.f, 0.f, 0.f};
    int base_r = blk * ROWS_PER_MOM + rsub;
    #pragma unroll 4
    for (int it = 0; it < ROWS_PER_MOM / 4; it++) {
        int r = base_r + it * 4;
        float4 v = reinterpret_cast<const float4*>(x + (size_t)r * D_FEAT)[cg];
        reinterpret_cast<float4*>(outx + (size_t)r * D_FEAT)[cg] = v;
        float vv[4] = {v.x, v.y, v.z, v.w};
        #pragma unroll
        for (int k = 0; k < 4; k++) {
            acc2(s[k], se[k], vv[k]);
            float p = vv[k] * vv[k];
            float perr = fmaf(vv[k], vv[k], -p);
            acc2(q[k], qe[k], p);
            qe[k] += perr;
        }
    }
    int prow = blk * 4 + rsub;
    #pragma unroll
    for (int k = 0; k < 4; k++)
        g_mompart[prow][cg * 4 + k] = make_float4(s[k], se[k], q[k], qe[k]);
}

// Parallel per-column moment reduction: one block per column, f64 tree.
__global__ void k_colstats() {
    __shared__ double shs[128], shq[128];
    int col = blockIdx.x;        // 256 blocks
    int t = threadIdx.x;         // 128 threads
    if (col == 0 && t == 0) g_nrefine = 0;
    double ds = 0.0, dq = 0.0;
    for (int b = t; b < NPART; b += 128) {
        float4 m = g_mompart[b][col];
        ds += (double)m.x + (double)m.y;
        dq += (double)m.z + (double)m.w;
    }
    shs[t] = ds; shq[t] = dq;
    __syncthreads();
    for (int off = 64; off; off >>= 1) {
        if (t < off) { shs[t] += shs[t + off]; shq[t] += shq[t + off]; }
        __syncthreads();
    }
    if (t == 0) {
        double S = shs[0], Q = shq[0];
        double mu_o  = S / (double)N_NODES;
        double var_o = (Q - S * S / (double)N_NODES) / (double)(N_NODES - 1);
        g_stats[col] = make_float2((float)mu_o, __fadd_rn((float)sqrt(var_o), 1e-8f));
    }
}

// Prompt stats + p_prime (f32 per-op match), write prompt rows, inner bits
// (f64, 8-way split per dot + shuffle reduce).
__global__ void k_finalize(const float* __restrict__ prompt, float* __restrict__ outx) {
    __shared__ float sh_pp[P_PROMPT][D_FEAT];   // 10 KB
    int tid = threadIdx.x;                       // 1024 threads

    if (tid < P_PROMPT) g_innerbits[tid] = 0;

    if (tid < D_FEAT) {
        int col = tid;
        float2 st = g_stats[col];
        float mu_of = st.x, sig_of = st.y;

        float pv[P_PROMPT];
        double ps = 0.0;
        for (int i = 0; i < P_PROMPT; i++) { pv[i] = prompt[i * D_FEAT + col]; ps += (double)pv[i]; }
        double mu_p = ps / (double)P_PROMPT;
        double pq = 0.0;
        for (int i = 0; i < P_PROMPT; i++) { double d = (double)pv[i] - mu_p; pq += d * d; }
        float mu_pf  = (float)mu_p;
        float sig_pf = __fadd_rn((float)sqrt(pq / (double)(P_PROMPT - 1)), 1e-8f);

        for (int i = 0; i < P_PROMPT; i++) {
            float pp = __fadd_rn(__fmul_rn(__fdiv_rn(__fsub_rn(pv[i], mu_pf), sig_pf), sig_of), mu_of);
            g_pprime[i * D_FEAT + col] = pp;
            sh_pp[i][col] = pp;
            outx[(size_t)(N_NODES + i) * D_FEAT + col] = pp;
        }
    }
    __syncthreads();

    if (tid < P_PROMPT * P_PROMPT * 8) {         // warps 0..24 fully active
        int pair = tid >> 3, l8 = tid & 7;
        int i = pair / P_PROMPT, j = pair % P_PROMPT;
        const float* a = sh_pp[i];
        const float* b = sh_pp[j];
        double s = 0.0;
        int c0 = l8 * 32;
        #pragma unroll 1
        for (int c = c0; c < c0 + 32; c++)
            s = fma((double)a[c], (double)b[c], s);
        #pragma unroll
        for (int off = 4; off; off >>= 1)
            s += __shfl_down_sync(0xffffffffu, s, off, 8);
        if (l8 == 0 && s > THR_INNER) atomicOr(&g_innerbits[i], 1u << j);
    }
}

// Cross similarities + fused per-chunk counts. 1 row/thread, single-buffered
// 16-col chunks; natural register allocation (~64 regs, 4 blocks/SM). R9 form.
__global__ void k_cross(const float* __restrict__ x) {
    extern __shared__ float dyn[];
    float4* sh_x  = reinterpret_cast<float4*>(dyn);       // [CROWS][F4PR]
    float*  sh_pp = dyn + TILE_F4 * 4;                    // [P_PROMPT][D_FEAT]
    __shared__ int wcnt[CTHREADS / 32][P_PROMPT];
    int tid = threadIdx.x;
    for (int t = tid; t < P_PROMPT * D_FEAT; t += CTHREADS) sh_pp[t] = g_pprime[t];
    int row0 = blockIdx.x * CROWS;

    float acc[P_PROMPT];
    #pragma unroll
    for (int i = 0; i < P_PROMPT; i++) acc[i] = 0.f;

    const float4* pp4 = reinterpret_cast<const float4*>(sh_pp);
    #pragma unroll 1
    for (int ch = 0; ch < NCH; ch++) {
        __syncthreads();
        #pragma unroll
        for (int l = 0; l < 4; l++) {
            int idx = l * CTHREADS + tid;
            int r = idx >> 2, f = idx & 3;
            int gr = row0 + r;
            float4 v = (gr < N_NODES)
                ? reinterpret_cast<const float4*>(x + (size_t)gr * D_FEAT)[ch * F4C + f]
                : make_float4(0.f, 0.f, 0.f, 0.f);
            sh_x[r * F4PR + f] = v;
        }
        __syncthreads();
        #pragma unroll
        for (int f = 0; f < F4C; f++) {
            float4 pv4[P_PROMPT];
            #pragma unroll
            for (int i = 0; i < P_PROMPT; i++)
                pv4[i] = pp4[i * (D_FEAT / 4) + ch * F4C + f];   // warp-broadcast LDS
            float4 xv = sh_x[tid * F4PR + f];
            #pragma unroll
            for (int i = 0; i < P_PROMPT; i++) {
                acc[i] = fmaf(xv.x, pv4[i].x, acc[i]);
                acc[i] = fmaf(xv.y, pv4[i].y, acc[i]);
                acc[i] = fmaf(xv.z, pv4[i].z, acc[i]);
                acc[i] = fmaf(xv.w, pv4[i].w, acc[i]);
            }
        }
    }

    int gr = row0 + tid;
    unsigned m = 0;
    if (gr < N_NODES) {
        #pragma unroll
        for (int i = 0; i < P_PROMPT; i++) {
            float a = acc[i];
            if (fabsf(a - THR_CROSS_F) < REFINE_WIN) {
                int pos = atomicAdd(&g_nrefine, 1);
                if (pos < REFINE_CAP) g_refine[pos] = make_int2(gr, i);
            }
            if ((double)a > THR_CROSS) m |= (1u << i);
        }
        g_crossmask[gr] = m;
    }

    // fused per-chunk per-i counts (chunk == blockIdx.x)
    int w = tid >> 5, lane = tid & 31;
    #pragma unroll
    for (int i = 0; i < P_PROMPT; i++) {
        unsigned bal = __ballot_sync(0xffffffffu, (m >> i) & 1u);
        if (lane == 0) wcnt[w][i] = __popc(bal);
    }
    __syncthreads();
    if (tid < P_PROMPT) {
        int t = 0;
        #pragma unroll
        for (int w2 = 0; w2 < CTHREADS / 32; w2++) t += wcnt[w2][tid];
        g_cpart[blockIdx.x * P_PROMPT + tid] = t;
    }
}

// Exact f64 recompute of near-threshold dots; fix mask bits AND chunk counts.
__global__ void k_refine(const float* __restrict__ x) {
    int t = blockIdx.x * blockDim.x + threadIdx.x;
    int n = g_nrefine;
    if (n > REFINE_CAP) n = REFINE_CAP;
    if (t >= n) return;
    int2 it = g_refine[t];
    const float* xr = x + (size_t)it.x * D_FEAT;
    const float* pp = g_pprime + it.y * D_FEAT;
    double s = 0.0;
    #pragma unroll 1
    for (int c = 0; c < D_FEAT; c++)
        s = fma((double)xr[c], (double)pp[c], s);
    unsigned bit = 1u << it.y;
    bool dec = (s > THR_CROSS);
    bool oldbit = (g_crossmask[it.x] >> it.y) & 1u;
    if (dec != oldbit) {
        if (dec) atomicOr(&g_crossmask[it.x], bit);
        else     atomicAnd(&g_crossmask[it.x], ~bit);
        atomicAdd(&g_cpart[(it.x / CHUNK) * P_PROMPT + it.y], dec ? 1 : -1);
    }
}

// Exclusive scan of chunk counts per i; totals -> g_ccnt.
__global__ void k_cross_spine() {
    __shared__ int sh[NCHUNK * P_PROMPT];   // ~31 KB
    for (int t = threadIdx.x; t < NCHUNK * P_PROMPT; t += blockDim.x) sh[t] = g_cpart[t];
    __syncthreads();
    if (threadIdx.x < P_PROMPT) {
        int i = threadIdx.x, run = 0;
        for (int c = 0; c < NCHUNK; c++) {
            int v = sh[c * P_PROMPT + i];
            g_choff[c * P_PROMPT + i] = run;
            run += v;
        }
        g_ccnt[i] = run;
    }
}

// hist also zeroes scan-0 lookback status (runs before fused scan 0 in-stream)
__global__ void k_hist(const int* __restrict__ src) {
    int g = blockIdx.x * blockDim.x + threadIdx.x;
    if (g < NB_SCAN) g_sstat[0][g] = 0ULL;
    if (g < E_ORIG) atomicAdd(&g_cnt[src[g]], 1);
}

// generic params, selected by mode (0: cnt->boff, 1: fcnt->outoff)
__device__ __forceinline__ void scan_params(int mode, const int*& in, int*& out, int& n) {
    if (mode == 0) { in = g_cnt;  out = g_boff;   n = N_NODES; }
    else           { in = g_fcnt; out = g_outoff; n = T_SENT;  }
}

// Single-pass decoupled-lookback exclusive scan. Status word packs
// (value << 2) | flag; flag: 0=empty, 1=aggregate, 2=inclusive-prefix.
__global__ void k_scan_fused(int mode) {
    const int* in; int* out; int n;
    scan_params(mode, in, out, n);
    __shared__ int sh[1024];
    __shared__ int sh_off;
    int tid = threadIdx.x;
    int bid = blockIdx.x;
    int g = bid * 1024 + tid;
    int v = (g < n) ? in[g] : 0;
    sh[tid] = v;
    __syncthreads();
    for (int off = 1; off < 1024; off <<= 1) {
        int t = (tid >= off) ? sh[tid - off] : 0;
        __syncthreads();
        sh[tid] += t;
        __syncthreads();
    }
    if (tid == 0) {
        int agg = sh[1023];
        if (bid == 0) {
            atomicExch(&g_sstat[mode][0], ((unsigned long long)(unsigned)agg << 2) | 2ULL);
            sh_off = 0;
        } else {
            atomicExch(&g_sstat[mode][bid], ((unsigned long long)(unsigned)agg << 2) | 1ULL);
            int excl = 0;
            int j = bid - 1;
            while (j >= 0) {
                unsigned long long s = *(volatile unsigned long long*)&g_sstat[mode][j];
                unsigned fl = (unsigned)(s & 3ULL);
                if (fl == 2u) { excl += (int)(s >> 2); break; }
                if (fl == 1u) { excl += (int)(s >> 2); j--; }
            }
            atomicExch(&g_sstat[mode][bid],
                       ((unsigned long long)(unsigned)(excl + agg) << 2) | 2ULL);
            sh_off = excl;
        }
    }
    __syncthreads();
    if (g < n) {
        int incl = sh[tid] + sh_off;
        int excl = incl - v;
        out[g] = excl;
        if (mode == 0) {
            g_cursor[g] = excl;
            g_cnt[g] = 0;             // re-zero for next graph replay (after last read)
        }
        if (g == n - 1) out[n] = incl;
    }
}

__global__ void k_scatter(const int* __restrict__ src, const int* __restrict__ dst) {
    int g = blockIdx.x * blockDim.x + threadIdx.x;
    if (g < E_ORIG) {
        int s = src[g];
        int pos = atomicAdd(&g_cursor[s], 1);
        g_bucket[pos] = dst[g];
    }
}

// Per-src insertion sort + dedup; working array in bank-conflict-free smem.
// Also zeroes scan-1 lookback status (runs before fused scan 1 in-stream).
__global__ void k_sortbuckets() {
    __shared__ int loc[BUCKET_CAP * 128];      // 32 KB; loc[k][tid] layout
    int tid = threadIdx.x;                     // 128 threads
    int j = blockIdx.x * 128 + tid;
    if (j < NB_SCAN) g_sstat[1][j] = 0ULL;
    #define LOC(k) loc[(k) * 128 + tid]
    if (j < N_NODES) {
        int base = g_boff[j];
        int len = g_boff[j + 1] - base;
        int L = 0;
        for (int k = 0; k < len; k++) {
            int v = g_bucket[base + k];
            int p = L;
            while (p > 0 && LOC(p - 1) > v) p--;
            if (p > 0 && LOC(p - 1) == v) continue;     // duplicate
            if (L < BUCKET_CAP) {
                for (int q = L; q > p; q--) LOC(q) = LOC(q - 1);
                LOC(p) = v;
                L++;
            }
        }
        for (int k = 0; k < L; k++) g_bucket[base + k] = LOC(k);
        g_fcnt[j] = L + __popc(g_crossmask[j]);
    } else if (j < T_SENT) {
        int i = j - N_NODES;
        g_fcnt[j] = g_ccnt[i] + __popc(g_innerbits[i]);
    }
    #undef LOC
}

// Emit edges with src < N: warp-per-node, lane-parallel coalesced stores.
__global__ void k_emit_orig(float* __restrict__ out_src, float* __restrict__ out_dst) {
    int wid = threadIdx.x >> 5;
    int lane = threadIdx.x & 31;
    int j = blockIdx.x * 8 + wid;
    if (j >= N_NODES) return;
    unsigned m = g_crossmask[j];
    int base = g_outoff[j];
    int bb = g_boff[j];
    int U = g_fcnt[j] - __popc(m);
    float fj = (float)j;
    for (int k = lane; k < U; k += 32) {
        out_src[base + k] = fj;
        out_dst[base + k] = (float)g_bucket[bb + k];
    }
    int nb = __popc(m);
    if (lane < nb) {
        unsigned mm = m;
        for (int t = 0; t < lane; t++) mm &= mm - 1;
        int b = __ffs(mm) - 1;
        out_src[base + U + lane] = fj;
        out_dst[base + U + lane] = (float)(N_NODES + b);
    }
}

// Emit cross edges (N+i, j) + inner prompt-prompt edges (block 0 tail).
__global__ void k_emit_cross(float* __restrict__ out_src, float* __restrict__ out_dst) {
    int chunk = blockIdx.x;
    int j = chunk * CHUNK + threadIdx.x;
    unsigned m = (j < N_NODES) ? g_crossmask[j] : 0u;
    __shared__ int wcnt[8][P_PROMPT];
    __shared__ int woff[8][P_PROMPT];
    int w = threadIdx.x >> 5, lane = threadIdx.x & 31;
    unsigned bal[P_PROMPT];
    #pragma unroll
    for (int i = 0; i < P_PROMPT; i++) {
        bal[i] = __ballot_sync(0xffffffffu, (m >> i) & 1u);
        if (lane == 0) wcnt[w][i] = __popc(bal[i]);
    }
    __syncthreads();
    if (threadIdx.x < P_PROMPT) {
        int run = 0;
        for (int w2 = 0; w2 < 8; w2++) { woff[w2][threadIdx.x] = run; run += wcnt[w2][threadIdx.x]; }
    }
    __syncthreads();
    unsigned ltmask = (1u << lane) - 1u;
    #pragma unroll
    for (int i = 0; i < P_PROMPT; i++) {
        if ((m >> i) & 1u) {
            int pos = g_outoff[N_NODES + i] + g_choff[chunk * P_PROMPT + i]
                      + woff[w][i] + __popc(bal[i] & ltmask);
            out_src[pos] = (float)(N_NODES + i);
            out_dst[pos] = (float)j;
        }
    }
    // inner prompt-prompt edges, emitted once by block 0
    if (chunk == 0 && threadIdx.x < P_PROMPT) {
        int i = threadIdx.x;
        int pos = g_outoff[N_NODES + i] + g_ccnt[i];
        unsigned b = g_innerbits[i];
        for (int jj = 0; jj < P_PROMPT; jj++) {
            if ((b >> jj) & 1u) {
                out_src[pos] = (float)(N_NODES + i);
                out_dst[pos] = (float)(N_NODES + jj);
                pos++;
            }
        }
    }
}

// Padding fill, float4-vectorized (tail handled scalar).
__global__ void k_fill(float* __restrict__ out_src, float* __restrict__ out_dst,
                       float* __restrict__ out_w) {
    int g4 = blockIdx.x * blockDim.x + threadIdx.x;   // float4 index
    int g = g4 * 4;
    if (g >= M_MAX) return;
    int M = __ldg(&g_outoff[T_SENT]);
    float4 sent = make_float4((float)T_SENT, (float)T_SENT, (float)T_SENT, (float)T_SENT);
    if (g + 4 <= M_MAX) {
        if (g >= M) {
            reinterpret_cast<float4*>(out_src)[g4] = sent;
            reinterpret_cast<float4*>(out_dst)[g4] = sent;
            reinterpret_cast<float4*>(out_w)[g4] = make_float4(0.f, 0.f, 0.f, 0.f);
        } else if (g + 4 > M) {
            for (int k = 0; k < 4; k++) {
                int idx = g + k;
                if (idx >= M) {
                    out_src[idx] = (float)T_SENT;
                    out_dst[idx] = (float)T_SENT;
                }
                out_w[idx] = (idx < M) ? 1.0f : 0.0f;
            }
        } else {
            reinterpret_cast<float4*>(out_w)[g4] = make_float4(1.f, 1.f, 1.f, 1.f);
        }
    } else {
        for (int idx = g; idx < M_MAX; idx++) {
            if (idx >= M) {
                out_src[idx] = (float)T_SENT;
                out_dst[idx] = (float)T_SENT;
            }
            out_w[idx] = (idx < M) ? 1.0f : 0.0f;
        }
    }
}

// ---------------- launch ----------------
extern "C" void kernel_launch(void* const* d_in, const int* in_sizes, int n_in,
                              void* d_out, int out_size) {
    (void)n_in; (void)out_size;
    const float* x  = (const float*)d_in[0];
    const int*   ei = (const int*)d_in[1];       // [2, E]: src then dst
    const float* pf = (const float*)d_in[2];
    const int* src = ei;
    const int* dst = ei + E_ORIG;
    (void)in_sizes;

    float* out     = (float*)d_out;
    float* out_x   = out;
    float* out_src = out + (size_t)T_SENT * D_FEAT;
    float* out_dst = out_src + M_MAX;
    float* out_w   = out_dst + M_MAX;

    cudaFuncSetAttribute(k_cross, cudaFuncAttributeMaxDynamicSharedMemorySize,
                         CROSS_SMEM_BYTES);

    cudaStream_t s1;
    cudaStreamCreateWithFlags(&s1, cudaStreamNonBlocking);
    cudaEvent_t evRoot, evE, evM, evF;
    cudaEventCreateWithFlags(&evRoot, cudaEventDisableTiming);
    cudaEventCreateWithFlags(&evE,   cudaEventDisableTiming);
    cudaEventCreateWithFlags(&evM,   cudaEventDisableTiming);
    cudaEventCreateWithFlags(&evF,   cudaEventDisableTiming);

    // fork side stream
    cudaEventRecord(evRoot, 0);
    cudaStreamWaitEvent(s1, evRoot, 0);

    // --- side stream s1: edge path (concurrent with x path) ---
    k_hist<<<(E_ORIG + 255) / 256, 256, 0, s1>>>(src);
    k_scan_fused<<<NB_SCAN, 1024, 0, s1>>>(0);
    k_scatter<<<(E_ORIG + 255) / 256, 256, 0, s1>>>(src, dst);
    cudaEventRecord(evE, s1);

    // --- x path (stream 0); copy fused in k_moments_copy (champion placement) ---
    k_moments_copy<<<NB_MOM, 256>>>(x, out_x);
    k_colstats<<<D_FEAT, 128>>>();
    k_finalize<<<1, 1024>>>(pf, out_x);
    k_cross<<<NBLK_CROSS, CTHREADS, CROSS_SMEM_BYTES>>>(x);
    k_refine<<<REFINE_CAP / 256, 256>>>(x);
    k_cross_spine<<<1, 1024>>>();

    // join: sortbuckets needs both paths
    cudaStreamWaitEvent(0, evE, 0);

    k_sortbuckets<<<(T_SENT + 127) / 128, 128>>>();
    k_scan_fused<<<NB_SCAN, 1024>>>(1);

    // fork fill (padding region, disjoint from emit writes) onto s1
    cudaEventRecord(evM, 0);
    cudaStreamWaitEvent(s1, evM, 0);
    k_fill<<<(M_MAX / 4 + 255) / 256, 256, 0, s1>>>(out_src, out_dst, out_w);

    k_emit_orig<<<(N_NODES + 7) / 8, 256>>>(out_src, out_dst);
    k_emit_cross<<<NCHUNK, 256>>>(out_src, out_dst);

    // join fill back
    cudaEventRecord(evF, s1);
    cudaStreamWaitEvent(0, evF, 0);

    cudaEventDestroy(evRoot);
    cudaEventDestroy(evE);
    cudaEventDestroy(evM);
    cudaEventDestroy(evF);
    cudaStreamDestroy(s1);
}

// round 15
// speedup vs baseline: 1.3194x; 1.0689x over previous
#include <cuda_runtime.h>
#include <cstdint>
#include <math.h>

#define N_NODES 200000
#define D_FEAT  256
#define P_PROMPT 10
#define E_ORIG  3200000
#define T_SENT  (N_NODES + P_PROMPT)                               // 200010
#define M_MAX   (E_ORIG + P_PROMPT*P_PROMPT + 2*P_PROMPT*N_NODES)  // 7200100

#define NB_MOM  1000
#define ROWS_PER_MOM (N_NODES / NB_MOM)   // 200
#define NPART (NB_MOM * 4)                // 4000 partial rows

#define CHUNK 256
#define NCHUNK ((N_NODES + CHUNK - 1) / CHUNK)  // 782

#define BUCKET_CAP 64
#define NB_SCAN 196   // ceil(200010/1024)

// thresholds: exact-logit equivalents of sigmoid(d) > (float)0.4 / (float)0.2
#define THR_CROSS (-0.4054650832728957)
#define THR_INNER (-1.3862943424934391)
#define THR_CROSS_F (-0.40546508f)
#define REFINE_WIN 3e-3f
#define REFINE_CAP 16384

// k_cross tiling: 256 threads, 1 row/thread, CROWS == CHUNK == 256
#define CTHREADS 256
#define CROWS 256
#define NCH   16
#define F4C   4
#define F4PR  5
#define TILE_F4 (CROWS * F4PR)                       // 1280 f4 = 20 KB
#define NBLK_CROSS ((N_NODES + CROWS - 1) / CROWS)   // 782 == NCHUNK
#define CROSS_SMEM_FLOATS (TILE_F4 * 4 + P_PROMPT * D_FEAT)
#define CROSS_SMEM_BYTES  (CROSS_SMEM_FLOATS * 4)    // 30720 B

// ---------------- static device scratch (no allocations allowed) ----------------
__device__ float4   g_mompart[NPART][D_FEAT];    // (sum, sum_err, sumsq, sumsq_err)
__device__ float2   g_stats[D_FEAT];             // (mu_of, sig_of)
__device__ float    g_pprime[P_PROMPT * D_FEAT];
__device__ unsigned g_crossmask[N_NODES];
__device__ unsigned g_innerbits[P_PROMPT];
__device__ int      g_cnt[N_NODES];              // zero-init; re-zeroed in fused scan(0)
__device__ int      g_boff[N_NODES + 1];
__device__ int      g_cursor[N_NODES];
__device__ int      g_bucket[E_ORIG];
__device__ int      g_ulen[N_NODES];             // unique original-dst count per node
__device__ int      g_outoff[T_SENT + 1];
__device__ int      g_cpart[NCHUNK * P_PROMPT];
__device__ int      g_choff[NCHUNK * P_PROMPT];
__device__ int      g_ccnt[P_PROMPT];
__device__ int2     g_refine[REFINE_CAP];
__device__ int      g_nrefine;
__device__ unsigned long long g_sstat[2][NB_SCAN];   // decoupled-lookback status

// ---------------- kernels ----------------

// 2Sum accumulate v into (s, e): exact error tracking in f32
__device__ __forceinline__ void acc2(float &s, float &e, float v) {
    float t = s + v;
    float z = t - s;
    e += (s - (t - z)) + (v - z);
    s = t;
}

// Pass 1: copy x -> out (x_combined head, float4) + per-column partial moments.
__global__ void k_moments_copy(const float* __restrict__ x, float* __restrict__ outx) {
    int blk = blockIdx.x;              // NB_MOM
    int cg   = threadIdx.x & 63;       // column group of 4
    int rsub = threadIdx.x >> 6;       // 0..3
    float s[4]  = {0.f, 0.f, 0.f, 0.f};
    float se[4] = {0.f, 0.f, 0.f, 0.f};
    float q[4]  = {0.f, 0.f, 0.f, 0.f};
    float qe[4] = {0.f, 0.f, 0.f, 0.f};
    int base_r = blk * ROWS_PER_MOM + rsub;
    #pragma unroll 4
    for (int it = 0; it < ROWS_PER_MOM / 4; it++) {
        int r = base_r + it * 4;
        float4 v = reinterpret_cast<const float4*>(x + (size_t)r * D_FEAT)[cg];
        reinterpret_cast<float4*>(outx + (size_t)r * D_FEAT)[cg] = v;
        float vv[4] = {v.x, v.y, v.z, v.w};
        #pragma unroll
        for (int k = 0; k < 4; k++) {
            acc2(s[k], se[k], vv[k]);
            float p = vv[k] * vv[k];
            float perr = fmaf(vv[k], vv[k], -p);
            acc2(q[k], qe[k], p);
            qe[k] += perr;
        }
    }
    int prow = blk * 4 + rsub;
    #pragma unroll
    for (int k = 0; k < 4; k++)
        g_mompart[prow][cg * 4 + k] = make_float4(s[k], se[k], q[k], qe[k]);
}

// Parallel per-column moment reduction: one block per column, f64 tree.
__global__ void k_colstats() {
    __shared__ double shs[128], shq[128];
    int col = blockIdx.x;        // 256 blocks
    int t = threadIdx.x;         // 128 threads
    if (col == 0 && t == 0) g_nrefine = 0;
    double ds = 0.0, dq = 0.0;
    for (int b = t; b < NPART; b += 128) {
        float4 m = g_mompart[b][col];
        ds += (double)m.x + (double)m.y;
        dq += (double)m.z + (double)m.w;
    }
    shs[t] = ds; shq[t] = dq;
    __syncthreads();
    for (int off = 64; off; off >>= 1) {
        if (t < off) { shs[t] += shs[t + off]; shq[t] += shq[t + off]; }
        __syncthreads();
    }
    if (t == 0) {
        double S = shs[0], Q = shq[0];
        double mu_o  = S / (double)N_NODES;
        double var_o = (Q - S * S / (double)N_NODES) / (double)(N_NODES - 1);
        g_stats[col] = make_float2((float)mu_o, __fadd_rn((float)sqrt(var_o), 1e-8f));
    }
}

// Prompt stats + p_prime (f32 per-op match), write prompt rows, inner bits.
__global__ void k_finalize(const float* __restrict__ prompt, float* __restrict__ outx) {
    __shared__ float sh_pp[P_PROMPT][D_FEAT];   // 10 KB
    int tid = threadIdx.x;                       // 1024 threads

    if (tid < P_PROMPT) g_innerbits[tid] = 0;

    if (tid < D_FEAT) {
        int col = tid;
        float2 st = g_stats[col];
        float mu_of = st.x, sig_of = st.y;

        float pv[P_PROMPT];
        double ps = 0.0;
        for (int i = 0; i < P_PROMPT; i++) { pv[i] = prompt[i * D_FEAT + col]; ps += (double)pv[i]; }
        double mu_p = ps / (double)P_PROMPT;
        double pq = 0.0;
        for (int i = 0; i < P_PROMPT; i++) { double d = (double)pv[i] - mu_p; pq += d * d; }
        float mu_pf  = (float)mu_p;
        float sig_pf = __fadd_rn((float)sqrt(pq / (double)(P_PROMPT - 1)), 1e-8f);

        for (int i = 0; i < P_PROMPT; i++) {
            float pp = __fadd_rn(__fmul_rn(__fdiv_rn(__fsub_rn(pv[i], mu_pf), sig_pf), sig_of), mu_of);
            g_pprime[i * D_FEAT + col] = pp;
            sh_pp[i][col] = pp;
            outx[(size_t)(N_NODES + i) * D_FEAT + col] = pp;
        }
    }
    __syncthreads();

    if (tid < P_PROMPT * P_PROMPT * 8) {         // warps 0..24 fully active
        int pair = tid >> 3, l8 = tid & 7;
        int i = pair / P_PROMPT, j = pair % P_PROMPT;
        const float* a = sh_pp[i];
        const float* b = sh_pp[j];
        double s = 0.0;
        int c0 = l8 * 32;
        #pragma unroll 1
        for (int c = c0; c < c0 + 32; c++)
            s = fma((double)a[c], (double)b[c], s);
        #pragma unroll
        for (int off = 4; off; off >>= 1)
            s += __shfl_down_sync(0xffffffffu, s, off, 8);
        if (l8 == 0 && s > THR_INNER) atomicOr(&g_innerbits[i], 1u << j);
    }
}

// Cross similarities + fused per-chunk counts. R9 champion form.
__global__ void k_cross(const float* __restrict__ x) {
    extern __shared__ float dyn[];
    float4* sh_x  = reinterpret_cast<float4*>(dyn);       // [CROWS][F4PR]
    float*  sh_pp = dyn + TILE_F4 * 4;                    // [P_PROMPT][D_FEAT]
    __shared__ int wcnt[CTHREADS / 32][P_PROMPT];
    int tid = threadIdx.x;
    for (int t = tid; t < P_PROMPT * D_FEAT; t += CTHREADS) sh_pp[t] = g_pprime[t];
    int row0 = blockIdx.x * CROWS;

    float acc[P_PROMPT];
    #pragma unroll
    for (int i = 0; i < P_PROMPT; i++) acc[i] = 0.f;

    const float4* pp4 = reinterpret_cast<const float4*>(sh_pp);
    #pragma unroll 1
    for (int ch = 0; ch < NCH; ch++) {
        __syncthreads();
        #pragma unroll
        for (int l = 0; l < 4; l++) {
            int idx = l * CTHREADS + tid;
            int r = idx >> 2, f = idx & 3;
            int gr = row0 + r;
            float4 v = (gr < N_NODES)
                ? reinterpret_cast<const float4*>(x + (size_t)gr * D_FEAT)[ch * F4C + f]
                : make_float4(0.f, 0.f, 0.f, 0.f);
            sh_x[r * F4PR + f] = v;
        }
        __syncthreads();
        #pragma unroll
        for (int f = 0; f < F4C; f++) {
            float4 pv4[P_PROMPT];
            #pragma unroll
            for (int i = 0; i < P_PROMPT; i++)
                pv4[i] = pp4[i * (D_FEAT / 4) + ch * F4C + f];   // warp-broadcast LDS
            float4 xv = sh_x[tid * F4PR + f];
            #pragma unroll
            for (int i = 0; i < P_PROMPT; i++) {
                acc[i] = fmaf(xv.x, pv4[i].x, acc[i]);
                acc[i] = fmaf(xv.y, pv4[i].y, acc[i]);
                acc[i] = fmaf(xv.z, pv4[i].z, acc[i]);
                acc[i] = fmaf(xv.w, pv4[i].w, acc[i]);
            }
        }
    }

    int gr = row0 + tid;
    unsigned m = 0;
    if (gr < N_NODES) {
        #pragma unroll
        for (int i = 0; i < P_PROMPT; i++) {
            float a = acc[i];
            if (fabsf(a - THR_CROSS_F) < REFINE_WIN) {
                int pos = atomicAdd(&g_nrefine, 1);
                if (pos < REFINE_CAP) g_refine[pos] = make_int2(gr, i);
            }
            if ((double)a > THR_CROSS) m |= (1u << i);
        }
        g_crossmask[gr] = m;
    }

    // fused per-chunk per-i counts (chunk == blockIdx.x)
    int w = tid >> 5, lane = tid & 31;
    #pragma unroll
    for (int i = 0; i < P_PROMPT; i++) {
        unsigned bal = __ballot_sync(0xffffffffu, (m >> i) & 1u);
        if (lane == 0) wcnt[w][i] = __popc(bal);
    }
    __syncthreads();
    if (tid < P_PROMPT) {
        int t = 0;
        #pragma unroll
        for (int w2 = 0; w2 < CTHREADS / 32; w2++) t += wcnt[w2][tid];
        g_cpart[blockIdx.x * P_PROMPT + tid] = t;
    }
}

// Exact f64 recompute of near-threshold dots; fix mask bits AND chunk counts.
__global__ void k_refine(const float* __restrict__ x) {
    int t = blockIdx.x * blockDim.x + threadIdx.x;
    int n = g_nrefine;
    if (n > REFINE_CAP) n = REFINE_CAP;
    if (t >= n) return;
    int2 it = g_refine[t];
    const float* xr = x + (size_t)it.x * D_FEAT;
    const float* pp = g_pprime + it.y * D_FEAT;
    double s = 0.0;
    #pragma unroll 1
    for (int c = 0; c < D_FEAT; c++)
        s = fma((double)xr[c], (double)pp[c], s);
    unsigned bit = 1u << it.y;
    bool dec = (s > THR_CROSS);
    bool oldbit = (g_crossmask[it.x] >> it.y) & 1u;
    if (dec != oldbit) {
        if (dec) atomicOr(&g_crossmask[it.x], bit);
        else     atomicAnd(&g_crossmask[it.x], ~bit);
        atomicAdd(&g_cpart[(it.x / CHUNK) * P_PROMPT + it.y], dec ? 1 : -1);
    }
}

// Exclusive scan of chunk counts per i; totals -> g_ccnt.
__global__ void k_cross_spine() {
    __shared__ int sh[NCHUNK * P_PROMPT];   // ~31 KB
    for (int t = threadIdx.x; t < NCHUNK * P_PROMPT; t += blockDim.x) sh[t] = g_cpart[t];
    __syncthreads();
    if (threadIdx.x < P_PROMPT) {
        int i = threadIdx.x, run = 0;
        for (int c = 0; c < NCHUNK; c++) {
            int v = sh[c * P_PROMPT + i];
            g_choff[c * P_PROMPT + i] = run;
            run += v;
        }
        g_ccnt[i] = run;
    }
}

// hist also zeroes scan-0 lookback status (runs before fused scan 0 in-stream)
__global__ void k_hist(const int* __restrict__ src) {
    int g = blockIdx.x * blockDim.x + threadIdx.x;
    if (g < NB_SCAN) g_sstat[0][g] = 0ULL;
    if (g < E_ORIG) atomicAdd(&g_cnt[src[g]], 1);
}

// Single-pass decoupled-lookback exclusive scan with WARP-PARALLEL lookback.
// Status packs (value << 2) | flag; flag: 0=empty, 1=aggregate, 2=incl-prefix.
// mode 0: in = g_cnt -> out g_boff (+cursor, cnt re-zero), n = N_NODES
// mode 1: in computed inline (ulen+popc(crossmask) / ccnt+popc(innerbits)),
//         out = g_outoff, n = T_SENT
__global__ void k_scan_fused(int mode) {
    int n = (mode == 0) ? N_NODES : T_SENT;
    int* out = (mode == 0) ? g_boff : g_outoff;
    __shared__ int sh[1024];
    __shared__ int sh_off;
    int tid = threadIdx.x;
    int bid = blockIdx.x;
    int g = bid * 1024 + tid;
    int v = 0;
    if (g < n) {
        if (mode == 0) {
            v = g_cnt[g];
        } else if (g < N_NODES) {
            v = g_ulen[g] + __popc(g_crossmask[g]);
        } else {
            int i = g - N_NODES;
            v = g_ccnt[i] + __popc(g_innerbits[i]);
        }
    }
    sh[tid] = v;
    __syncthreads();
    for (int off = 1; off < 1024; off <<= 1) {
        int t = (tid >= off) ? sh[tid - off] : 0;
        __syncthreads();
        sh[tid] += t;
        __syncthreads();
    }
    int agg = sh[1023];
    if (tid == 0 && bid > 0)
        atomicExch(&g_sstat[mode][bid], ((unsigned long long)(unsigned)agg << 2) | 1ULL);
    // warp 0: parallel lookback
    if (tid < 32) {
        int lane = tid;
        int excl = 0;
        if (bid > 0) {
            int j = bid - 1;
            bool done = false;
            while (!done) {
                int idx = j - lane;
                unsigned long long s;
                unsigned fl;
                do {
                    s = (idx >= 0) ? *(volatile unsigned long long*)&g_sstat[mode][idx]
                                   : 2ULL;   // virtual prefix 0 below block 0
                    fl = (unsigned)(s & 3ULL);
                } while (fl == 0u);
                unsigned pball = __ballot_sync(0xffffffffu, fl == 2u);
                int contrib;
                if (pball) {
                    int fp = __ffs(pball) - 1;            // nearest inclusive prefix
                    contrib = (lane <= fp) ? (int)(s >> 2) : 0;
                    done = true;
                } else {
                    contrib = (int)(s >> 2);              // 32 aggregates, step back
                    j -= 32;
                }
                #pragma unroll
                for (int off = 16; off; off >>= 1)
                    contrib += __shfl_xor_sync(0xffffffffu, contrib, off);
                excl += contrib;
            }
        }
        if (lane == 0) {
            atomicExch(&g_sstat[mode][bid],
                       ((unsigned long long)(unsigned)(excl + agg) << 2) | 2ULL);
            sh_off = excl;
        }
    }
    __syncthreads();
    if (g < n) {
        int incl = sh[tid] + sh_off;
        int excl = incl - v;
        out[g] = excl;
        if (mode == 0) {
            g_cursor[g] = excl;
            g_cnt[g] = 0;             // re-zero for next graph replay (after last read)
        }
        if (g == n - 1) out[n] = incl;
    }
}

__global__ void k_scatter(const int* __restrict__ src, const int* __restrict__ dst) {
    int g = blockIdx.x * blockDim.x + threadIdx.x;
    if (g < E_ORIG) {
        int s = src[g];
        int pos = atomicAdd(&g_cursor[s], 1);
        g_bucket[pos] = dst[g];
    }
}

// Per-src insertion sort + dedup; PURE edge-path (runs on s1, overlapped with
// k_cross). Writes unique-count to g_ulen. Also zeroes scan-1 status.
__global__ void k_sortbuckets() {
    __shared__ int loc[BUCKET_CAP * 128];      // 32 KB; loc[k][tid] layout
    int tid = threadIdx.x;                     // 128 threads
    int j = blockIdx.x * 128 + tid;
    if (j < NB_SCAN) g_sstat[1][j] = 0ULL;
    #define LOC(k) loc[(k) * 128 + tid]
    if (j < N_NODES) {
        int base = g_boff[j];
        int len = g_boff[j + 1] - base;
        int L = 0;
        for (int k = 0; k < len; k++) {
            int v = g_bucket[base + k];
            int p = L;
            while (p > 0 && LOC(p - 1) > v) p--;
            if (p > 0 && LOC(p - 1) == v) continue;     // duplicate
            if (L < BUCKET_CAP) {
                for (int q = L; q > p; q--) LOC(q) = LOC(q - 1);
                LOC(p) = v;
                L++;
            }
        }
        for (int k = 0; k < L; k++) g_bucket[base + k] = LOC(k);
        g_ulen[j] = L;
    }
    #undef LOC
}

// Emit edges with src < N: warp-per-node, lane-parallel coalesced stores.
__global__ void k_emit_orig(float* __restrict__ out_src, float* __restrict__ out_dst) {
    int wid = threadIdx.x >> 5;
    int lane = threadIdx.x & 31;
    int j = blockIdx.x * 8 + wid;
    if (j >= N_NODES) return;
    unsigned m = g_crossmask[j];
    int base = g_outoff[j];
    int bb = g_boff[j];
    int U = g_ulen[j];
    float fj = (float)j;
    for (int k = lane; k < U; k += 32) {
        out_src[base + k] = fj;
        out_dst[base + k] = (float)g_bucket[bb + k];
    }
    int nb = __popc(m);
    if (lane < nb) {
        unsigned mm = m;
        for (int t = 0; t < lane; t++) mm &= mm - 1;
        int b = __ffs(mm) - 1;
        out_src[base + U + lane] = fj;
        out_dst[base + U + lane] = (float)(N_NODES + b);
    }
}

// Emit cross edges (N+i, j) + inner prompt-prompt edges (block 0 tail).
__global__ void k_emit_cross(float* __restrict__ out_src, float* __restrict__ out_dst) {
    int chunk = blockIdx.x;
    int j = chunk * CHUNK + threadIdx.x;
    unsigned m = (j < N_NODES) ? g_crossmask[j] : 0u;
    __shared__ int wcnt[8][P_PROMPT];
    __shared__ int woff[8][P_PROMPT];
    int w = threadIdx.x >> 5, lane = threadIdx.x & 31;
    unsigned bal[P_PROMPT];
    #pragma unroll
    for (int i = 0; i < P_PROMPT; i++) {
        bal[i] = __ballot_sync(0xffffffffu, (m >> i) & 1u);
        if (lane == 0) wcnt[w][i] = __popc(bal[i]);
    }
    __syncthreads();
    if (threadIdx.x < P_PROMPT) {
        int run = 0;
        for (int w2 = 0; w2 < 8; w2++) { woff[w2][threadIdx.x] = run; run += wcnt[w2][threadIdx.x]; }
    }
    __syncthreads();
    unsigned ltmask = (1u << lane) - 1u;
    #pragma unroll
    for (int i = 0; i < P_PROMPT; i++) {
        if ((m >> i) & 1u) {
            int pos = g_outoff[N_NODES + i] + g_choff[chunk * P_PROMPT + i]
                      + woff[w][i] + __popc(bal[i] & ltmask);
            out_src[pos] = (float)(N_NODES + i);
            out_dst[pos] = (float)j;
        }
    }
    // inner prompt-prompt edges, emitted once by block 0
    if (chunk == 0 && threadIdx.x < P_PROMPT) {
        int i = threadIdx.x;
        int pos = g_outoff[N_NODES + i] + g_ccnt[i];
        unsigned b = g_innerbits[i];
        for (int jj = 0; jj < P_PROMPT; jj++) {
            if ((b >> jj) & 1u) {
                out_src[pos] = (float)(N_NODES + i);
                out_dst[pos] = (float)(N_NODES + jj);
                pos++;
            }
        }
    }
}

// Padding fill, float4-vectorized (tail handled scalar).
__global__ void k_fill(float* __restrict__ out_src, float* __restrict__ out_dst,
                       float* __restrict__ out_w) {
    int g4 = blockIdx.x * blockDim.x + threadIdx.x;   // float4 index
    int g = g4 * 4;
    if (g >= M_MAX) return;
    int M = __ldg(&g_outoff[T_SENT]);
    float4 sent = make_float4((float)T_SENT, (float)T_SENT, (float)T_SENT, (float)T_SENT);
    if (g + 4 <= M_MAX) {
        if (g >= M) {
            reinterpret_cast<float4*>(out_src)[g4] = sent;
            reinterpret_cast<float4*>(out_dst)[g4] = sent;
            reinterpret_cast<float4*>(out_w)[g4] = make_float4(0.f, 0.f, 0.f, 0.f);
        } else if (g + 4 > M) {
            for (int k = 0; k < 4; k++) {
                int idx = g + k;
                if (idx >= M) {
                    out_src[idx] = (float)T_SENT;
                    out_dst[idx] = (float)T_SENT;
                }
                out_w[idx] = (idx < M) ? 1.0f : 0.0f;
            }
        } else {
            reinterpret_cast<float4*>(out_w)[g4] = make_float4(1.f, 1.f, 1.f, 1.f);
        }
    } else {
        for (int idx = g; idx < M_MAX; idx++) {
            if (idx >= M) {
                out_src[idx] = (float)T_SENT;
                out_dst[idx] = (float)T_SENT;
            }
            out_w[idx] = (idx < M) ? 1.0f : 0.0f;
        }
    }
}

// ---------------- launch ----------------
extern "C" void kernel_launch(void* const* d_in, const int* in_sizes, int n_in,
                              void* d_out, int out_size) {
    (void)n_in; (void)out_size;
    const float* x  = (const float*)d_in[0];
    const int*   ei = (const int*)d_in[1];       // [2, E]: src then dst
    const float* pf = (const float*)d_in[2];
    const int* src = ei;
    const int* dst = ei + E_ORIG;
    (void)in_sizes;

    float* out     = (float*)d_out;
    float* out_x   = out;
    float* out_src = out + (size_t)T_SENT * D_FEAT;
    float* out_dst = out_src + M_MAX;
    float* out_w   = out_dst + M_MAX;

    cudaFuncSetAttribute(k_cross, cudaFuncAttributeMaxDynamicSharedMemorySize,
                         CROSS_SMEM_BYTES);

    cudaStream_t s1;
    cudaStreamCreateWithFlags(&s1, cudaStreamNonBlocking);
    cudaEvent_t evRoot, evE, evM, evF;
    cudaEventCreateWithFlags(&evRoot, cudaEventDisableTiming);
    cudaEventCreateWithFlags(&evE,   cudaEventDisableTiming);
    cudaEventCreateWithFlags(&evM,   cudaEventDisableTiming);
    cudaEventCreateWithFlags(&evF,   cudaEventDisableTiming);

    // fork side stream
    cudaEventRecord(evRoot, 0);
    cudaStreamWaitEvent(s1, evRoot, 0);

    // --- side stream s1: full edge path incl. sortbuckets (pure edge deps) ---
    k_hist<<<(E_ORIG + 255) / 256, 256, 0, s1>>>(src);
    k_scan_fused<<<NB_SCAN, 1024, 0, s1>>>(0);
    k_scatter<<<(E_ORIG + 255) / 256, 256, 0, s1>>>(src, dst);
    k_sortbuckets<<<(N_NODES + 127) / 128, 128, 0, s1>>>();
    cudaEventRecord(evE, s1);

    // --- x path (stream 0) ---
    k_moments_copy<<<NB_MOM, 256>>>(x, out_x);
    k_colstats<<<D_FEAT, 128>>>();
    k_finalize<<<1, 1024>>>(pf, out_x);
    k_cross<<<NBLK_CROSS, CTHREADS, CROSS_SMEM_BYTES>>>(x);
    k_refine<<<REFINE_CAP / 256, 256>>>(x);
    k_cross_spine<<<1, 1024>>>();

    // join: scan1 needs ulen (s1) + crossmask/ccnt/innerbits (stream 0)
    cudaStreamWaitEvent(0, evE, 0);
    k_scan_fused<<<NB_SCAN, 1024>>>(1);

    // fork fill (padding region, disjoint from emit writes) onto s1
    cudaEventRecord(evM, 0);
    cudaStreamWaitEvent(s1, evM, 0);
    k_fill<<<(M_MAX / 4 + 255) / 256, 256, 0, s1>>>(out_src, out_dst, out_w);

    k_emit_orig<<<(N_NODES + 7) / 8, 256>>>(out_src, out_dst);
    k_emit_cross<<<NCHUNK, 256>>>(out_src, out_dst);

    // join fill back
    cudaEventRecord(evF, s1);
    cudaStreamWaitEvent(0, evF, 0);

    cudaEventDestroy(evRoot);
    cudaEventDestroy(evE);
    cudaEventDestroy(evM);
    cudaEventDestroy(evF);
    cudaStreamDestroy(s1);
}